// round 15
// baseline (speedup 1.0000x reference)
#include <cuda_runtime.h>
#include <cuda_fp16.h>
#include <cstdint>

#define UNITS   128
#define GATES   512
#define IN_DIM  512
#define BATCH   128
#define SEQ     1024

// scratch (no allocation allowed -> device globals)
// g_xw layout: [t][b][pos] with pos = 4*(col&127) + (col>>7)  (gate-permuted)
__device__ float  g_xw[(size_t)SEQ * BATCH * GATES];
__device__ __half g_WTh[(size_t)GATES * IN_DIM];       // W^T: [gate][i]
__device__ __half g_Uh[(size_t)UNITS * GATES];         // U, PERMUTED cols: [k][4u+q]

__device__ __forceinline__ float tanhfast(float x) {
    float y;
    asm("tanh.approx.f32 %0, %1;" : "=f"(y) : "f"(x));
    return y;
}

// coalesced W transpose (32x32 smem tile) fp32 -> fp16
__global__ __launch_bounds__(256) void conv_w(const float* __restrict__ W) {
    __shared__ float tile[32][33];
    const int bx = blockIdx.x * 32;   // j block
    const int by = blockIdx.y * 32;   // i block
    const int tx = threadIdx.x, ty4 = threadIdx.y;   // 32 x 8
    #pragma unroll
    for (int r = 0; r < 4; r++) {
        int ty = ty4 * 4 + r;
        tile[ty][tx] = W[(size_t)(by + ty) * GATES + bx + tx];
    }
    __syncthreads();
    #pragma unroll
    for (int r = 0; r < 4; r++) {
        int ty = ty4 * 4 + r;
        g_WTh[(size_t)(bx + ty) * IN_DIM + by + tx] = __float2half(tile[tx][ty]);
    }
}
// U conversion, gate-permuted columns: dst[k][4u+q] = U[k][128q+u]
__global__ void conv_u(const float* __restrict__ U) {
    int idx = blockIdx.x * 256 + threadIdx.x;          // 128*512
    int k = idx >> 9, j = idx & 511;
    g_Uh[(size_t)k * GATES + 4 * (j & 127) + (j >> 7)] = __float2half(U[idx]);
}

// ---------------- Phase A: xW GEMM (round-6 proven config) ---------------
#define BM 128
#define BN 128
#define BK 32
#define LDA 40

__global__ __launch_bounds__(256) void gemm_xw(const float* __restrict__ x,
                                               const float* __restrict__ bias) {
    __shared__ __align__(16) __half As[2][BM][LDA];
    __shared__ __align__(16) __half Bs[2][BN][LDA];

    const int tid = threadIdx.x;
    const int nb  = blockIdx.x;      // 0..3  gate-column block
    const int t   = blockIdx.y;      // 0..1023 timestep
    const int lane = tid & 31, wid = tid >> 5;
    const int wm = wid & 3, wn = wid >> 2;     // 4(m) x 2(n) warps
    const int g  = lane >> 2, tg2 = (lane & 3) * 2;

    float acc[2][8][4];
    #pragma unroll
    for (int a = 0; a < 2; a++)
        #pragma unroll
        for (int q = 0; q < 8; q++)
            #pragma unroll
            for (int c = 0; c < 4; c++) acc[a][q][c] = 0.f;

    const int ar = tid >> 3;               // A row (batch) 0..31 (+32*i)
    const int ak = (tid & 7) * 4;          // A k offset
    const float* aptr = x + ((size_t)ar * SEQ + t) * IN_DIM + ak;
    const int bn_ = tid >> 1;              // B row (gate col)
    const int bk_ = (tid & 1) * 16;        // B k offset (halfs)
    const __half* bptr = g_WTh + (size_t)(nb * BN + bn_) * IN_DIM + bk_;

    float4 av[4];
    uint4  bv[2];

    auto ldg = [&](int kt) {
        const float* ap = aptr + kt * BK;
        #pragma unroll
        for (int i = 0; i < 4; i++)
            av[i] = *(const float4*)(ap + (size_t)i * 32 * SEQ * IN_DIM);
        const __half* bp = bptr + kt * BK;
        bv[0] = *(const uint4*)(bp);
        bv[1] = *(const uint4*)(bp + 8);
    };
    auto sts = [&](int buf) {
        #pragma unroll
        for (int i = 0; i < 4; i++) {
            __half2 h0 = __floats2half2_rn(av[i].x, av[i].y);
            __half2 h1 = __floats2half2_rn(av[i].z, av[i].w);
            uint2 u;
            u.x = *reinterpret_cast<unsigned*>(&h0);
            u.y = *reinterpret_cast<unsigned*>(&h1);
            *(uint2*)&As[buf][ar + 32 * i][ak] = u;
        }
        *(uint4*)&Bs[buf][bn_][bk_]     = bv[0];
        *(uint4*)&Bs[buf][bn_][bk_ + 8] = bv[1];
    };

    ldg(0); sts(0); __syncthreads();

    #pragma unroll 1
    for (int kt = 0; kt < 16; kt++) {
        const int cur = kt & 1;
        if (kt < 15) ldg(kt + 1);

        #pragma unroll
        for (int ks = 0; ks < 2; ks++) {
            const int k0 = ks * 16;
            uint32_t afr[2][4], bfr[8][2];
            #pragma unroll
            for (int mt = 0; mt < 2; mt++) {
                const int m0 = wm * 32 + mt * 16;
                afr[mt][0] = *(const uint32_t*)&As[cur][m0 + g    ][k0 + tg2    ];
                afr[mt][1] = *(const uint32_t*)&As[cur][m0 + g + 8][k0 + tg2    ];
                afr[mt][2] = *(const uint32_t*)&As[cur][m0 + g    ][k0 + tg2 + 8];
                afr[mt][3] = *(const uint32_t*)&As[cur][m0 + g + 8][k0 + tg2 + 8];
            }
            #pragma unroll
            for (int nt = 0; nt < 8; nt++) {
                const int n0 = wn * 64 + nt * 8 + g;
                bfr[nt][0] = *(const uint32_t*)&Bs[cur][n0][k0 + tg2    ];
                bfr[nt][1] = *(const uint32_t*)&Bs[cur][n0][k0 + tg2 + 8];
            }
            #pragma unroll
            for (int mt = 0; mt < 2; mt++)
                #pragma unroll
                for (int nt = 0; nt < 8; nt++) {
                    float* c = acc[mt][nt];
                    asm volatile(
                        "mma.sync.aligned.m16n8k16.row.col.f32.f16.f16.f32 "
                        "{%0,%1,%2,%3}, {%4,%5,%6,%7}, {%8,%9}, {%0,%1,%2,%3};\n"
                        : "+f"(c[0]), "+f"(c[1]), "+f"(c[2]), "+f"(c[3])
                        : "r"(afr[mt][0]), "r"(afr[mt][1]), "r"(afr[mt][2]), "r"(afr[mt][3]),
                          "r"(bfr[nt][0]), "r"(bfr[nt][1]));
                }
        }
        if (kt < 15) { sts(1 - cur); __syncthreads(); }
    }

    // epilogue, gate-permuted store: pos(col) = 4*(col & 127) + nb
    #pragma unroll
    for (int mt = 0; mt < 2; mt++) {
        const int r0 = wm * 32 + mt * 16 + g;
        #pragma unroll
        for (int nt = 0; nt < 8; nt++) {
            const int col  = nb * BN + wn * 64 + nt * 8 + tg2;
            const int pos  = 4 * (col & 127) + nb;
            const float b0 = __ldg(&bias[col]), b1 = __ldg(&bias[col + 1]);
            float* row0 = &g_xw[((size_t)t * BATCH + r0    ) * GATES];
            float* row1 = &g_xw[((size_t)t * BATCH + r0 + 8) * GATES];
            row0[pos]     = acc[mt][nt][0] + b0;
            row0[pos + 4] = acc[mt][nt][1] + b1;
            row1[pos]     = acc[mt][nt][2] + b0;
            row1[pos + 4] = acc[mt][nt][3] + b1;
        }
    }
}

// ---------------- Phase B: recurrence, unit-major pbuf -------------------
// 1 CTA / batch, 1024 thr. All layouts gate-permuted (pos = 4u+q).
// Phase 1 (32 warps): thread (kg = tid>>7, cg = tid&127) owns the 4 gates
// of unit cg over k-chunk [16kg,16kg+16); fp16 partials, one fp32 flush;
// stores one float4 (i,f,g,o) to pbuf[cg][kg] (row pitch 9 float4 = 144B,
// conflict-free STS/LDS.128).
// Phase 2 (threads < 128, fused): thread u: 8x LDS.128 reduce + 4 tanh +
// cell update + h splat; xw read as one permuted float4.

__global__ __launch_bounds__(1024) void lstm_rec(float* __restrict__ out) {
    __shared__ __align__(16) __half2 hsp[UNITS];        // splatted (h_k, h_k)
    __shared__ __align__(16) float pbuf[UNITS][36];     // [unit][9 float4 slots]

    const int tid = threadIdx.x;
    const int kg  = tid >> 7;        // 0..7
    const int cg  = tid & 127;       // 0..127 (unit)
    const int b   = blockIdx.x;

    // U slice -> registers: 4 permuted cols (gates of unit cg) x 16 k
    __half2 ureg[16][2];
    {
        const __half* ub = g_Uh + (size_t)(kg * 16) * GATES + cg * 4;
        #pragma unroll
        for (int k = 0; k < 16; k++)
            *(uint2*)&ureg[k][0] = *(const uint2*)(ub + (size_t)k * GATES);
    }
    if (tid < UNITS) hsp[tid] = __float2half2_rn(0.f);
    float c = 0.f, hlast = 0.f;
    __syncthreads();

    // xW prefetch: thread u reads its unit's 4 permuted gates as float4
    const float* xwp = g_xw + (size_t)b * GATES + 4 * tid;
    float4 xw = make_float4(0.f, 0.f, 0.f, 0.f);
    if (tid < UNITS) xw = *(const float4*)xwp;
    xwp += (size_t)BATCH * GATES;

    const __half2 z2 = __float2half2_rn(0.f);

    for (int step = 0; step < SEQ; step++) {
        // ---- phase 1: matvec partial over k-chunk of 16, single fp32 flush
        const uint4* h4 = (const uint4*)hsp + kg * 4;
        __half2 a0 = z2, a1 = z2;                    // (i,f) and (g,o)
        #pragma unroll
        for (int e = 0; e < 4; e++) {
            union { uint4 v; __half2 h[4]; } hv;
            hv.v = h4[e];                            // broadcast LDS.128
            #pragma unroll
            for (int j = 0; j < 4; j++) {
                a0 = __hfma2(hv.h[j], ureg[e * 4 + j][0], a0);
                a1 = __hfma2(hv.h[j], ureg[e * 4 + j][1], a1);
            }
        }
        const float2 t0 = __half22float2(a0);
        const float2 t1 = __half22float2(a1);
        *(float4*)&pbuf[cg][kg * 4] = make_float4(t0.x, t0.y, t1.x, t1.y);
        __syncthreads();

        // ---- phase 2: fused reduce + gates + cell (thread u owns unit u)
        if (tid < UNITS) {
            float4 s = xw;
            #pragma unroll
            for (int k = 0; k < 8; k++) {
                const float4 p = *(const float4*)&pbuf[tid][k * 4];
                s.x += p.x; s.y += p.y; s.z += p.z; s.w += p.w;
            }
            const float zi = tanhfast(s.x);
            const float zf = tanhfast(s.y);
            const float zg = tanhfast(s.z);
            const float zo = tanhfast(s.w);
            c = zf * c + zi * zg;
            hlast = zo * tanhfast(c);
            hsp[tid] = __float2half2_rn(hlast);
            if (step + 1 < SEQ) xw = *(const float4*)xwp;
            xwp += (size_t)BATCH * GATES;
        }
        __syncthreads();
    }
    if (tid < UNITS) out[(size_t)b * UNITS + tid] = hlast;
}

// ---------------- launch -------------------------------------------------
extern "C" void kernel_launch(void* const* d_in, const int* in_sizes, int n_in,
                              void* d_out, int out_size) {
    const float* x = (const float*)d_in[0];
    const float* W = (const float*)d_in[1];
    const float* U = (const float*)d_in[2];
    const float* b = (const float*)d_in[3];
    float* out = (float*)d_out;

    conv_w<<<dim3(16, 16), dim3(32, 8)>>>(W);
    conv_u<<<(UNITS * GATES) / 256, 256>>>(U);
    gemm_xw<<<dim3(4, SEQ), 256>>>(x, b);
    lstm_rec<<<BATCH, 1024>>>(out);
}

// round 16
// speedup vs baseline: 1.1291x; 1.1291x over previous
#include <cuda_runtime.h>
#include <cuda_fp16.h>
#include <cstdint>

#define UNITS   128
#define GATES   512
#define IN_DIM  512
#define BATCH   128
#define SEQ     1024

// scratch (no allocation allowed -> device globals)
// g_xw layout: [t][b][pos] with pos = 4*(col&127) + (col>>7)  (gate-permuted)
__device__ float  g_xw[(size_t)SEQ * BATCH * GATES];
__device__ __half g_WTh[(size_t)GATES * IN_DIM];       // W^T: [gate][i]
__device__ __half g_Uh[(size_t)UNITS * GATES];         // U:   [k][j] (natural)

__device__ __forceinline__ float tanhfast(float x) {
    float y;
    asm("tanh.approx.f32 %0, %1;" : "=f"(y) : "f"(x));
    return y;
}

// coalesced W transpose (32x32 smem tile) fp32 -> fp16
__global__ __launch_bounds__(256) void conv_w(const float* __restrict__ W) {
    __shared__ float tile[32][33];
    const int bx = blockIdx.x * 32;   // j block
    const int by = blockIdx.y * 32;   // i block
    const int tx = threadIdx.x, ty4 = threadIdx.y;   // 32 x 8
    #pragma unroll
    for (int r = 0; r < 4; r++) {
        int ty = ty4 * 4 + r;
        tile[ty][tx] = W[(size_t)(by + ty) * GATES + bx + tx];
    }
    __syncthreads();
    #pragma unroll
    for (int r = 0; r < 4; r++) {
        int ty = ty4 * 4 + r;
        g_WTh[(size_t)(bx + ty) * IN_DIM + by + tx] = __float2half(tile[tx][ty]);
    }
}
__global__ void conv_u(const float* __restrict__ U) {
    int idx = blockIdx.x * 256 + threadIdx.x;          // 128*512
    g_Uh[idx] = __float2half(U[idx]);
}

// ---------------- Phase A: xW GEMM (round-6 proven config) ---------------
#define BM 128
#define BN 128
#define BK 32
#define LDA 40

__global__ __launch_bounds__(256) void gemm_xw(const float* __restrict__ x,
                                               const float* __restrict__ bias) {
    __shared__ __align__(16) __half As[2][BM][LDA];
    __shared__ __align__(16) __half Bs[2][BN][LDA];

    const int tid = threadIdx.x;
    const int nb  = blockIdx.x;      // 0..3  gate-column block
    const int t   = blockIdx.y;      // 0..1023 timestep
    const int lane = tid & 31, wid = tid >> 5;
    const int wm = wid & 3, wn = wid >> 2;     // 4(m) x 2(n) warps
    const int g  = lane >> 2, tg2 = (lane & 3) * 2;

    float acc[2][8][4];
    #pragma unroll
    for (int a = 0; a < 2; a++)
        #pragma unroll
        for (int q = 0; q < 8; q++)
            #pragma unroll
            for (int c = 0; c < 4; c++) acc[a][q][c] = 0.f;

    const int ar = tid >> 3;               // A row (batch) 0..31 (+32*i)
    const int ak = (tid & 7) * 4;          // A k offset
    const float* aptr = x + ((size_t)ar * SEQ + t) * IN_DIM + ak;
    const int bn_ = tid >> 1;              // B row (gate col)
    const int bk_ = (tid & 1) * 16;        // B k offset (halfs)
    const __half* bptr = g_WTh + (size_t)(nb * BN + bn_) * IN_DIM + bk_;

    float4 av[4];
    uint4  bv[2];

    auto ldg = [&](int kt) {
        const float* ap = aptr + kt * BK;
        #pragma unroll
        for (int i = 0; i < 4; i++)
            av[i] = *(const float4*)(ap + (size_t)i * 32 * SEQ * IN_DIM);
        const __half* bp = bptr + kt * BK;
        bv[0] = *(const uint4*)(bp);
        bv[1] = *(const uint4*)(bp + 8);
    };
    auto sts = [&](int buf) {
        #pragma unroll
        for (int i = 0; i < 4; i++) {
            __half2 h0 = __floats2half2_rn(av[i].x, av[i].y);
            __half2 h1 = __floats2half2_rn(av[i].z, av[i].w);
            uint2 u;
            u.x = *reinterpret_cast<unsigned*>(&h0);
            u.y = *reinterpret_cast<unsigned*>(&h1);
            *(uint2*)&As[buf][ar + 32 * i][ak] = u;
        }
        *(uint4*)&Bs[buf][bn_][bk_]     = bv[0];
        *(uint4*)&Bs[buf][bn_][bk_ + 8] = bv[1];
    };

    ldg(0); sts(0); __syncthreads();

    #pragma unroll 1
    for (int kt = 0; kt < 16; kt++) {
        const int cur = kt & 1;
        if (kt < 15) ldg(kt + 1);

        #pragma unroll
        for (int ks = 0; ks < 2; ks++) {
            const int k0 = ks * 16;
            uint32_t afr[2][4], bfr[8][2];
            #pragma unroll
            for (int mt = 0; mt < 2; mt++) {
                const int m0 = wm * 32 + mt * 16;
                afr[mt][0] = *(const uint32_t*)&As[cur][m0 + g    ][k0 + tg2    ];
                afr[mt][1] = *(const uint32_t*)&As[cur][m0 + g + 8][k0 + tg2    ];
                afr[mt][2] = *(const uint32_t*)&As[cur][m0 + g    ][k0 + tg2 + 8];
                afr[mt][3] = *(const uint32_t*)&As[cur][m0 + g + 8][k0 + tg2 + 8];
            }
            #pragma unroll
            for (int nt = 0; nt < 8; nt++) {
                const int n0 = wn * 64 + nt * 8 + g;
                bfr[nt][0] = *(const uint32_t*)&Bs[cur][n0][k0 + tg2    ];
                bfr[nt][1] = *(const uint32_t*)&Bs[cur][n0][k0 + tg2 + 8];
            }
            #pragma unroll
            for (int mt = 0; mt < 2; mt++)
                #pragma unroll
                for (int nt = 0; nt < 8; nt++) {
                    float* c = acc[mt][nt];
                    asm volatile(
                        "mma.sync.aligned.m16n8k16.row.col.f32.f16.f16.f32 "
                        "{%0,%1,%2,%3}, {%4,%5,%6,%7}, {%8,%9}, {%0,%1,%2,%3};\n"
                        : "+f"(c[0]), "+f"(c[1]), "+f"(c[2]), "+f"(c[3])
                        : "r"(afr[mt][0]), "r"(afr[mt][1]), "r"(afr[mt][2]), "r"(afr[mt][3]),
                          "r"(bfr[nt][0]), "r"(bfr[nt][1]));
                }
        }
        if (kt < 15) { sts(1 - cur); __syncthreads(); }
    }

    // epilogue, gate-permuted store: pos(col) = 4*(col & 127) + nb
    #pragma unroll
    for (int mt = 0; mt < 2; mt++) {
        const int r0 = wm * 32 + mt * 16 + g;
        #pragma unroll
        for (int nt = 0; nt < 8; nt++) {
            const int col  = nb * BN + wn * 64 + nt * 8 + tg2;
            const int pos  = 4 * (col & 127) + nb;
            const float b0 = __ldg(&bias[col]), b1 = __ldg(&bias[col + 1]);
            float* row0 = &g_xw[((size_t)t * BATCH + r0    ) * GATES];
            float* row1 = &g_xw[((size_t)t * BATCH + r0 + 8) * GATES];
            row0[pos]     = acc[mt][nt][0] + b0;
            row0[pos + 4] = acc[mt][nt][1] + b1;
            row1[pos]     = acc[mt][nt][2] + b0;
            row1[pos + 4] = acc[mt][nt][3] + b1;
        }
    }
}

// ---------------- Phase B: recurrence (round-14 proven config) -----------
// 1 CTA / batch, 1024 thr. Phase 1 (32 warps): thread (kg = tid>>7,
// cg = tid&127) owns natural gate cols [4cg,4cg+4) over k-chunk
// [16kg,16kg+16); fp16 partials, ONE fp32 flush per 16-k chunk. Phase 2
// (threads < 128, fused): thread u reduces pbuf[k][u+128q], does all 4
// tanh + cell update, splats h; xw read as one permuted float4.

__global__ __launch_bounds__(1024) void lstm_rec(float* __restrict__ out) {
    __shared__ __align__(16) __half2 hsp[UNITS];     // splatted (h_k, h_k)
    __shared__ __align__(16) float pbuf[8][GATES];   // k-split partials (16KB)

    const int tid = threadIdx.x;
    const int kg  = tid >> 7;        // 0..7
    const int cg  = tid & 127;       // 0..127
    const int b   = blockIdx.x;

    __half2 ureg[16][2];
    {
        const __half* ub = g_Uh + (size_t)(kg * 16) * GATES + cg * 4;
        #pragma unroll
        for (int k = 0; k < 16; k++)
            *(uint2*)&ureg[k][0] = *(const uint2*)(ub + (size_t)k * GATES);
    }
    if (tid < UNITS) hsp[tid] = __float2half2_rn(0.f);
    float c = 0.f, hlast = 0.f;
    __syncthreads();

    // xW prefetch: thread u reads its unit's 4 permuted gates as float4
    const float* xwp = g_xw + (size_t)b * GATES + 4 * tid;
    float4 xw = make_float4(0.f, 0.f, 0.f, 0.f);
    if (tid < UNITS) xw = *(const float4*)xwp;
    xwp += (size_t)BATCH * GATES;

    const __half2 z2 = __float2half2_rn(0.f);

    for (int step = 0; step < SEQ; step++) {
        // ---- phase 1: matvec partial over k-chunk of 16, single fp32 flush
        const uint4* h4 = (const uint4*)hsp + kg * 4;
        __half2 a0 = z2, a1 = z2;
        #pragma unroll
        for (int e = 0; e < 4; e++) {
            union { uint4 v; __half2 h[4]; } hv;
            hv.v = h4[e];                                // broadcast LDS.128
            #pragma unroll
            for (int j = 0; j < 4; j++) {
                a0 = __hfma2(hv.h[j], ureg[e * 4 + j][0], a0);
                a1 = __hfma2(hv.h[j], ureg[e * 4 + j][1], a1);
            }
        }
        const float2 t0 = __half22float2(a0);
        const float2 t1 = __half22float2(a1);
        *(float4*)&pbuf[kg][cg * 4] = make_float4(t0.x, t0.y, t1.x, t1.y);
        __syncthreads();

        // ---- phase 2: fused reduce + gates + cell (thread u owns unit u)
        if (tid < UNITS) {
            float z[4];
            #pragma unroll
            for (int q = 0; q < 4; q++) {
                float s = (&xw.x)[q];
                #pragma unroll
                for (int k = 0; k < 8; k++) s += pbuf[k][tid + 128 * q];
                z[q] = tanhfast(s);
            }
            c = z[1] * c + z[0] * z[2];
            hlast = z[3] * tanhfast(c);
            hsp[tid] = __float2half2_rn(hlast);
            if (step + 1 < SEQ) xw = *(const float4*)xwp;
            xwp += (size_t)BATCH * GATES;
        }
        __syncthreads();
    }
    if (tid < UNITS) out[(size_t)b * UNITS + tid] = hlast;
}

// ---------------- launch -------------------------------------------------
extern "C" void kernel_launch(void* const* d_in, const int* in_sizes, int n_in,
                              void* d_out, int out_size) {
    const float* x = (const float*)d_in[0];
    const float* W = (const float*)d_in[1];
    const float* U = (const float*)d_in[2];
    const float* b = (const float*)d_in[3];
    float* out = (float*)d_out;

    conv_w<<<dim3(16, 16), dim3(32, 8)>>>(W);
    conv_u<<<(UNITS * GATES) / 256, 256>>>(U);
    gemm_xw<<<dim3(4, SEQ), 256>>>(x, b);
    lstm_rec<<<BATCH, 1024>>>(out);
}

// round 17
// speedup vs baseline: 1.1486x; 1.0172x over previous
#include <cuda_runtime.h>
#include <cuda_fp16.h>
#include <cstdint>

#define UNITS   128
#define GATES   512
#define IN_DIM  512
#define BATCH   128
#define SEQ     1024

// scratch (no allocation allowed -> device globals)
// g_xw layout: [t][b][pos] with pos = 4*(col&127) + (col>>7)  (gate-permuted)
__device__ float  g_xw[(size_t)SEQ * BATCH * GATES];
__device__ __half g_WTh[(size_t)GATES * IN_DIM];       // W^T: [gate][i]
__device__ __half g_Uh[(size_t)UNITS * GATES];         // U:   [k][j] (natural)

__device__ __forceinline__ float tanhfast(float x) {
    float y;
    asm("tanh.approx.f32 %0, %1;" : "=f"(y) : "f"(x));
    return y;
}

// coalesced W transpose (32x32 smem tile) fp32 -> fp16
__global__ __launch_bounds__(256) void conv_w(const float* __restrict__ W) {
    __shared__ float tile[32][33];
    const int bx = blockIdx.x * 32;   // j block
    const int by = blockIdx.y * 32;   // i block
    const int tx = threadIdx.x, ty4 = threadIdx.y;   // 32 x 8
    #pragma unroll
    for (int r = 0; r < 4; r++) {
        int ty = ty4 * 4 + r;
        tile[ty][tx] = W[(size_t)(by + ty) * GATES + bx + tx];
    }
    __syncthreads();
    #pragma unroll
    for (int r = 0; r < 4; r++) {
        int ty = ty4 * 4 + r;
        g_WTh[(size_t)(bx + ty) * IN_DIM + by + tx] = __float2half(tile[tx][ty]);
    }
}
__global__ void conv_u(const float* __restrict__ U) {
    int idx = blockIdx.x * 256 + threadIdx.x;          // 128*512
    g_Uh[idx] = __float2half(U[idx]);
}

// ---------------- Phase A: xW GEMM (round-6 proven config) ---------------
#define BM 128
#define BN 128
#define BK 32
#define LDA 40

__global__ __launch_bounds__(256) void gemm_xw(const float* __restrict__ x,
                                               const float* __restrict__ bias) {
    __shared__ __align__(16) __half As[2][BM][LDA];
    __shared__ __align__(16) __half Bs[2][BN][LDA];

    const int tid = threadIdx.x;
    const int nb  = blockIdx.x;      // 0..3  gate-column block
    const int t   = blockIdx.y;      // 0..1023 timestep
    const int lane = tid & 31, wid = tid >> 5;
    const int wm = wid & 3, wn = wid >> 2;     // 4(m) x 2(n) warps
    const int g  = lane >> 2, tg2 = (lane & 3) * 2;

    float acc[2][8][4];
    #pragma unroll
    for (int a = 0; a < 2; a++)
        #pragma unroll
        for (int q = 0; q < 8; q++)
            #pragma unroll
            for (int c = 0; c < 4; c++) acc[a][q][c] = 0.f;

    const int ar = tid >> 3;               // A row (batch) 0..31 (+32*i)
    const int ak = (tid & 7) * 4;          // A k offset
    const float* aptr = x + ((size_t)ar * SEQ + t) * IN_DIM + ak;
    const int bn_ = tid >> 1;              // B row (gate col)
    const int bk_ = (tid & 1) * 16;        // B k offset (halfs)
    const __half* bptr = g_WTh + (size_t)(nb * BN + bn_) * IN_DIM + bk_;

    float4 av[4];
    uint4  bv[2];

    auto ldg = [&](int kt) {
        const float* ap = aptr + kt * BK;
        #pragma unroll
        for (int i = 0; i < 4; i++)
            av[i] = *(const float4*)(ap + (size_t)i * 32 * SEQ * IN_DIM);
        const __half* bp = bptr + kt * BK;
        bv[0] = *(const uint4*)(bp);
        bv[1] = *(const uint4*)(bp + 8);
    };
    auto sts = [&](int buf) {
        #pragma unroll
        for (int i = 0; i < 4; i++) {
            __half2 h0 = __floats2half2_rn(av[i].x, av[i].y);
            __half2 h1 = __floats2half2_rn(av[i].z, av[i].w);
            uint2 u;
            u.x = *reinterpret_cast<unsigned*>(&h0);
            u.y = *reinterpret_cast<unsigned*>(&h1);
            *(uint2*)&As[buf][ar + 32 * i][ak] = u;
        }
        *(uint4*)&Bs[buf][bn_][bk_]     = bv[0];
        *(uint4*)&Bs[buf][bn_][bk_ + 8] = bv[1];
    };

    ldg(0); sts(0); __syncthreads();

    #pragma unroll 1
    for (int kt = 0; kt < 16; kt++) {
        const int cur = kt & 1;
        if (kt < 15) ldg(kt + 1);

        #pragma unroll
        for (int ks = 0; ks < 2; ks++) {
            const int k0 = ks * 16;
            uint32_t afr[2][4], bfr[8][2];
            #pragma unroll
            for (int mt = 0; mt < 2; mt++) {
                const int m0 = wm * 32 + mt * 16;
                afr[mt][0] = *(const uint32_t*)&As[cur][m0 + g    ][k0 + tg2    ];
                afr[mt][1] = *(const uint32_t*)&As[cur][m0 + g + 8][k0 + tg2    ];
                afr[mt][2] = *(const uint32_t*)&As[cur][m0 + g    ][k0 + tg2 + 8];
                afr[mt][3] = *(const uint32_t*)&As[cur][m0 + g + 8][k0 + tg2 + 8];
            }
            #pragma unroll
            for (int nt = 0; nt < 8; nt++) {
                const int n0 = wn * 64 + nt * 8 + g;
                bfr[nt][0] = *(const uint32_t*)&Bs[cur][n0][k0 + tg2    ];
                bfr[nt][1] = *(const uint32_t*)&Bs[cur][n0][k0 + tg2 + 8];
            }
            #pragma unroll
            for (int mt = 0; mt < 2; mt++)
                #pragma unroll
                for (int nt = 0; nt < 8; nt++) {
                    float* c = acc[mt][nt];
                    asm volatile(
                        "mma.sync.aligned.m16n8k16.row.col.f32.f16.f16.f32 "
                        "{%0,%1,%2,%3}, {%4,%5,%6,%7}, {%8,%9}, {%0,%1,%2,%3};\n"
                        : "+f"(c[0]), "+f"(c[1]), "+f"(c[2]), "+f"(c[3])
                        : "r"(afr[mt][0]), "r"(afr[mt][1]), "r"(afr[mt][2]), "r"(afr[mt][3]),
                          "r"(bfr[nt][0]), "r"(bfr[nt][1]));
                }
        }
        if (kt < 15) { sts(1 - cur); __syncthreads(); }
    }

    // epilogue, gate-permuted store: pos(col) = 4*(col & 127) + nb
    #pragma unroll
    for (int mt = 0; mt < 2; mt++) {
        const int r0 = wm * 32 + mt * 16 + g;
        #pragma unroll
        for (int nt = 0; nt < 8; nt++) {
            const int col  = nb * BN + wn * 64 + nt * 8 + tg2;
            const int pos  = 4 * (col & 127) + nb;
            const float b0 = __ldg(&bias[col]), b1 = __ldg(&bias[col + 1]);
            float* row0 = &g_xw[((size_t)t * BATCH + r0    ) * GATES];
            float* row1 = &g_xw[((size_t)t * BATCH + r0 + 8) * GATES];
            row0[pos]     = acc[mt][nt][0] + b0;
            row0[pos + 4] = acc[mt][nt][1] + b1;
            row1[pos]     = acc[mt][nt][2] + b0;
            row1[pos + 4] = acc[mt][nt][3] + b1;
        }
    }
}

// ---------------- Phase B: recurrence (r14 + dual-chain phase 1) ---------
// 1 CTA / batch, 1024 thr. Phase 1 (32 warps): thread (kg = tid>>7,
// cg = tid&127) owns natural gate cols [4cg,4cg+4) over k-chunk
// [16kg,16kg+16); TWO independent 8-deep HFMA2 chains merged with HADD2,
// one fp32 flush per 16-k chunk. Phase 2 (threads < 128, fused): thread u
// reduces pbuf[k][u+128q], 4 tanh + cell update, splats h; permuted
// float4 xw prefetch.

__global__ __launch_bounds__(1024) void lstm_rec(float* __restrict__ out) {
    __shared__ __align__(16) __half2 hsp[UNITS];     // splatted (h_k, h_k)
    __shared__ __align__(16) float pbuf[8][GATES];   // k-split partials (16KB)

    const int tid = threadIdx.x;
    const int kg  = tid >> 7;        // 0..7
    const int cg  = tid & 127;       // 0..127
    const int b   = blockIdx.x;

    __half2 ureg[16][2];
    {
        const __half* ub = g_Uh + (size_t)(kg * 16) * GATES + cg * 4;
        #pragma unroll
        for (int k = 0; k < 16; k++)
            *(uint2*)&ureg[k][0] = *(const uint2*)(ub + (size_t)k * GATES);
    }
    if (tid < UNITS) hsp[tid] = __float2half2_rn(0.f);
    float c = 0.f, hlast = 0.f;
    __syncthreads();

    // xW prefetch: thread u reads its unit's 4 permuted gates as float4
    const float* xwp = g_xw + (size_t)b * GATES + 4 * tid;
    float4 xw = make_float4(0.f, 0.f, 0.f, 0.f);
    if (tid < UNITS) xw = *(const float4*)xwp;
    xwp += (size_t)BATCH * GATES;

    const __half2 z2 = __float2half2_rn(0.f);

    #pragma unroll 2
    for (int step = 0; step < SEQ; step++) {
        // ---- phase 1: two independent 8-deep HFMA2 chains, merged once
        const uint4* h4 = (const uint4*)hsp + kg * 4;
        __half2 a0 = z2, a1 = z2, c0 = z2, c1 = z2;
        #pragma unroll
        for (int e = 0; e < 2; e++) {
            union { uint4 v; __half2 h[4]; } hv;
            hv.v = h4[e];                                // broadcast LDS.128
            #pragma unroll
            for (int j = 0; j < 4; j++) {
                a0 = __hfma2(hv.h[j], ureg[e * 4 + j][0], a0);
                a1 = __hfma2(hv.h[j], ureg[e * 4 + j][1], a1);
            }
        }
        #pragma unroll
        for (int e = 2; e < 4; e++) {
            union { uint4 v; __half2 h[4]; } hv;
            hv.v = h4[e];                                // broadcast LDS.128
            #pragma unroll
            for (int j = 0; j < 4; j++) {
                c0 = __hfma2(hv.h[j], ureg[e * 4 + j][0], c0);
                c1 = __hfma2(hv.h[j], ureg[e * 4 + j][1], c1);
            }
        }
        a0 = __hadd2(a0, c0);
        a1 = __hadd2(a1, c1);
        const float2 t0 = __half22float2(a0);
        const float2 t1 = __half22float2(a1);
        *(float4*)&pbuf[kg][cg * 4] = make_float4(t0.x, t0.y, t1.x, t1.y);
        __syncthreads();

        // ---- phase 2: fused reduce + gates + cell (thread u owns unit u)
        if (tid < UNITS) {
            float z[4];
            #pragma unroll
            for (int q = 0; q < 4; q++) {
                float s = (&xw.x)[q];
                #pragma unroll
                for (int k = 0; k < 8; k++) s += pbuf[k][tid + 128 * q];
                z[q] = tanhfast(s);
            }
            c = z[1] * c + z[0] * z[2];
            hlast = z[3] * tanhfast(c);
            hsp[tid] = __float2half2_rn(hlast);
            if (step + 1 < SEQ) xw = *(const float4*)xwp;
            xwp += (size_t)BATCH * GATES;
        }
        __syncthreads();
    }
    if (tid < UNITS) out[(size_t)b * UNITS + tid] = hlast;
}

// ---------------- launch -------------------------------------------------
extern "C" void kernel_launch(void* const* d_in, const int* in_sizes, int n_in,
                              void* d_out, int out_size) {
    const float* x = (const float*)d_in[0];
    const float* W = (const float*)d_in[1];
    const float* U = (const float*)d_in[2];
    const float* b = (const float*)d_in[3];
    float* out = (float*)d_out;

    conv_w<<<dim3(16, 16), dim3(32, 8)>>>(W);
    conv_u<<<(UNITS * GATES) / 256, 256>>>(U);
    gemm_xw<<<dim3(4, SEQ), 256>>>(x, b);
    lstm_rec<<<BATCH, 1024>>>(out);
}